// round 1
// baseline (speedup 1.0000x reference)
#include <cuda_runtime.h>
#include <cuda_bf16.h>

// ---------------------------------------------------------------------------
// SelectiveSSM: y = scan(x, softplus(dt), B_in, C_in, A) + x*D
//   proj = x @ Wx^T            (8192 x 96)
//   dt   = softplus(proj[:, :64] @ dt_W^T + dt_b)   (8192 x 1024)
//   scan over L=2048, state (d=1024, s=16) per batch
// ---------------------------------------------------------------------------

#define BATCH   4
#define SEQLEN  2048
#define DMODEL  1024
#define DSTATE  16
#define DTRANK  64
#define NPROJ   96          // DTRANK + 2*DSTATE
#define NROWS   (BATCH * SEQLEN)   // 8192

// device scratch (allocation-free rule: use __device__ globals)
__device__ float g_proj[NROWS * NPROJ];    // 3 MB
__device__ float g_dt[NROWS * DMODEL];     // 32 MB

// ---------------------------------------------------------------------------
// Kernel 1: proj = x @ Wx^T.  M=8192, N=96, K=1024.
// Block tile 64(m) x 96(n), BK=32, 256 threads, 4x6 micro-tile.
// ---------------------------------------------------------------------------
__global__ __launch_bounds__(256, 4)
void proj_gemm_kernel(const float* __restrict__ x, const float* __restrict__ Wx)
{
    __shared__ float xs[32][65];   // [k][m], padded (conflict-free)
    __shared__ float ws[32][97];   // [k][n], padded

    const int block_m = blockIdx.x * 64;
    const int t  = threadIdx.x;
    const int ty = t >> 4;        // 0..15 (m groups of 4)
    const int tx = t & 15;        // 0..15 (n groups of 6)

    float acc[4][6];
#pragma unroll
    for (int i = 0; i < 4; i++)
#pragma unroll
        for (int j = 0; j < 6; j++) acc[i][j] = 0.f;

    for (int k0 = 0; k0 < DMODEL; k0 += 32) {
        // load x tile: 64 rows x 32 k (512 float4, 2 per thread)
#pragma unroll
        for (int i = t; i < 64 * 8; i += 256) {
            int m  = i >> 3;
            int kq = i & 7;
            float4 v = *(const float4*)&x[(size_t)(block_m + m) * DMODEL + k0 + kq * 4];
            xs[kq * 4 + 0][m] = v.x;
            xs[kq * 4 + 1][m] = v.y;
            xs[kq * 4 + 2][m] = v.z;
            xs[kq * 4 + 3][m] = v.w;
        }
        // load W tile: 96 rows(n) x 32 k (768 float4, 3 per thread)
#pragma unroll
        for (int i = t; i < 96 * 8; i += 256) {
            int n  = i >> 3;
            int kq = i & 7;
            float4 v = *(const float4*)&Wx[(size_t)n * DMODEL + k0 + kq * 4];
            ws[kq * 4 + 0][n] = v.x;
            ws[kq * 4 + 1][n] = v.y;
            ws[kq * 4 + 2][n] = v.z;
            ws[kq * 4 + 3][n] = v.w;
        }
        __syncthreads();

#pragma unroll
        for (int kk = 0; kk < 32; kk++) {
            float a[4], b[6];
#pragma unroll
            for (int i = 0; i < 4; i++) a[i] = xs[kk][ty * 4 + i];
#pragma unroll
            for (int j = 0; j < 6; j++) b[j] = ws[kk][tx * 6 + j];
#pragma unroll
            for (int i = 0; i < 4; i++)
#pragma unroll
                for (int j = 0; j < 6; j++) acc[i][j] = fmaf(a[i], b[j], acc[i][j]);
        }
        __syncthreads();
    }

#pragma unroll
    for (int i = 0; i < 4; i++)
#pragma unroll
        for (int j = 0; j < 6; j++)
            g_proj[(size_t)(block_m + ty * 4 + i) * NPROJ + tx * 6 + j] = acc[i][j];
}

// ---------------------------------------------------------------------------
// Kernel 2: dt = softplus(dt_r @ dt_W^T + dt_b).  M=8192, N=1024, K=64.
// Block tile 64 x 64, single K pass, 256 threads, 4x4 micro-tile.
// ---------------------------------------------------------------------------
__device__ __forceinline__ float softplusf(float z)
{
    return (z > 20.f) ? z : log1pf(__expf(z));
}

__global__ __launch_bounds__(256, 4)
void dt_gemm_kernel(const float* __restrict__ dt_W, const float* __restrict__ dt_b)
{
    __shared__ float rs[64][65];   // [k][m]
    __shared__ float ws[64][65];   // [k][n]

    const int block_m = blockIdx.x * 64;
    const int block_n = blockIdx.y * 64;
    const int t  = threadIdx.x;
    const int ty = t >> 4;
    const int tx = t & 15;

    // load dt_r tile (from g_proj cols [0,64)): 64 rows x 64 k = 1024 float4
#pragma unroll
    for (int i = t; i < 64 * 16; i += 256) {
        int m  = i >> 4;
        int kq = i & 15;
        float4 v = *(const float4*)&g_proj[(size_t)(block_m + m) * NPROJ + kq * 4];
        rs[kq * 4 + 0][m] = v.x;
        rs[kq * 4 + 1][m] = v.y;
        rs[kq * 4 + 2][m] = v.z;
        rs[kq * 4 + 3][m] = v.w;
    }
    // load dt_W tile: 64 d-rows x 64 r
#pragma unroll
    for (int i = t; i < 64 * 16; i += 256) {
        int n  = i >> 4;
        int kq = i & 15;
        float4 v = *(const float4*)&dt_W[(size_t)(block_n + n) * DTRANK + kq * 4];
        ws[kq * 4 + 0][n] = v.x;
        ws[kq * 4 + 1][n] = v.y;
        ws[kq * 4 + 2][n] = v.z;
        ws[kq * 4 + 3][n] = v.w;
    }
    __syncthreads();

    float acc[4][4];
#pragma unroll
    for (int i = 0; i < 4; i++)
#pragma unroll
        for (int j = 0; j < 4; j++) acc[i][j] = 0.f;

#pragma unroll
    for (int kk = 0; kk < 64; kk++) {
        float a[4], b[4];
#pragma unroll
        for (int i = 0; i < 4; i++) a[i] = rs[kk][ty * 4 + i];
#pragma unroll
        for (int j = 0; j < 4; j++) b[j] = ws[kk][tx * 4 + j];
#pragma unroll
        for (int i = 0; i < 4; i++)
#pragma unroll
            for (int j = 0; j < 4; j++) acc[i][j] = fmaf(a[i], b[j], acc[i][j]);
    }

    float bias[4];
#pragma unroll
    for (int j = 0; j < 4; j++) bias[j] = dt_b[block_n + tx * 4 + j];

#pragma unroll
    for (int i = 0; i < 4; i++)
#pragma unroll
        for (int j = 0; j < 4; j++)
            g_dt[(size_t)(block_m + ty * 4 + i) * DMODEL + block_n + tx * 4 + j] =
                softplusf(acc[i][j] + bias[j]);
}

// ---------------------------------------------------------------------------
// Kernel 3: selective scan. One thread per (d, s) state element.
// Block = 128 threads = 8 d-channels; grid = (128 d-blocks, 4 batches).
// y-reduction over s=16 via 4x shfl_xor; dA via single MUFU.EX2.
// ---------------------------------------------------------------------------
__device__ __forceinline__ float ex2f(float z)
{
    float r;
    asm("ex2.approx.ftz.f32 %0, %1;" : "=f"(r) : "f"(z));
    return r;
}

__global__ __launch_bounds__(128, 8)
void scan_kernel(const float* __restrict__ x, const float* __restrict__ A_log,
                 const float* __restrict__ Dp, float* __restrict__ out)
{
    const int b    = blockIdx.y;
    const int t    = threadIdx.x;
    const int s    = t & 15;
    const int dloc = t >> 4;
    const int d    = blockIdx.x * 8 + dloc;

    const float LOG2E = 1.4426950408889634f;
    const float A2 = -__expf(A_log[d * DSTATE + s]) * LOG2E;   // A * log2(e)
    const float Dd = Dp[d];

    const size_t base = (size_t)b * SEQLEN * DMODEL + d;
    const float* __restrict__ xb  = x    + base;
    const float* __restrict__ dtb = g_dt + base;
    const float* __restrict__ pb  = g_proj + (size_t)b * SEQLEN * NPROJ;
    float* __restrict__ ob = out + base;

    float h = 0.f;
#pragma unroll 2
    for (int l = 0; l < SEQLEN; l++) {
        float dtv = dtb[(size_t)l * DMODEL];
        float xv  = xb[(size_t)l * DMODEL];
        float Bs  = pb[l * NPROJ + DTRANK + s];
        float Cs  = pb[l * NPROJ + DTRANK + DSTATE + s];

        float dA = ex2f(dtv * A2);
        h = fmaf(h, dA, dtv * xv * Bs);

        float p = h * Cs;
        p += __shfl_xor_sync(0xffffffffu, p, 8);
        p += __shfl_xor_sync(0xffffffffu, p, 4);
        p += __shfl_xor_sync(0xffffffffu, p, 2);
        p += __shfl_xor_sync(0xffffffffu, p, 1);

        if (s == 0) ob[(size_t)l * DMODEL] = fmaf(xv, Dd, p);
    }
}

// ---------------------------------------------------------------------------
extern "C" void kernel_launch(void* const* d_in, const int* in_sizes, int n_in,
                              void* d_out, int out_size)
{
    const float* x     = (const float*)d_in[0];
    const float* A_log = (const float*)d_in[1];
    const float* D     = (const float*)d_in[2];
    const float* Wx    = (const float*)d_in[3];
    const float* dt_W  = (const float*)d_in[4];
    const float* dt_b  = (const float*)d_in[5];
    float* out = (float*)d_out;

    proj_gemm_kernel<<<NROWS / 64, 256>>>(x, Wx);
    dt_gemm_kernel<<<dim3(NROWS / 64, DMODEL / 64), 256>>>(dt_W, dt_b);
    scan_kernel<<<dim3(DMODEL / 8, BATCH), 128>>>(x, A_log, D, out);
}

// round 2
// speedup vs baseline: 2.8391x; 2.8391x over previous
#include <cuda_runtime.h>
#include <cuda_bf16.h>

// ---------------------------------------------------------------------------
// SelectiveSSM: y = scan(x, softplus(dt), B_in, C_in, A) + x*D
// ---------------------------------------------------------------------------

#define BATCH   4
#define SEQLEN  2048
#define DMODEL  1024
#define DSTATE  16
#define DTRANK  64
#define NPROJ   96          // DTRANK + 2*DSTATE
#define NROWS   (BATCH * SEQLEN)   // 8192

// device scratch (allocation-free rule: use __device__ globals)
__device__ float g_proj[NROWS * NPROJ];    // 3 MB
__device__ float g_dt[NROWS * DMODEL];     // 32 MB

// ---------------------------------------------------------------------------
// Kernel 1: proj = x @ Wx^T.  M=8192, N=96, K=1024.
// Block tile 32(m) x 96(n), BK=32, 128 threads, 4x6 micro-tile. Grid=256.
// ---------------------------------------------------------------------------
__global__ __launch_bounds__(128, 8)
void proj_gemm_kernel(const float* __restrict__ x, const float* __restrict__ Wx)
{
    __shared__ float xs[32][33];   // [k][m], padded
    __shared__ float ws[32][97];   // [k][n], padded

    const int block_m = blockIdx.x * 32;
    const int t  = threadIdx.x;
    const int ty = t >> 4;        // 0..7  (m groups of 4)
    const int tx = t & 15;        // 0..15 (n groups of 6)

    float acc[4][6];
#pragma unroll
    for (int i = 0; i < 4; i++)
#pragma unroll
        for (int j = 0; j < 6; j++) acc[i][j] = 0.f;

    for (int k0 = 0; k0 < DMODEL; k0 += 32) {
        // load x tile: 32 rows x 32 k = 256 float4, 2 per thread
#pragma unroll
        for (int i = t; i < 32 * 8; i += 128) {
            int m  = i >> 3;
            int kq = i & 7;
            float4 v = *(const float4*)&x[(size_t)(block_m + m) * DMODEL + k0 + kq * 4];
            xs[kq * 4 + 0][m] = v.x;
            xs[kq * 4 + 1][m] = v.y;
            xs[kq * 4 + 2][m] = v.z;
            xs[kq * 4 + 3][m] = v.w;
        }
        // load W tile: 96 rows(n) x 32 k = 768 float4, 6 per thread
#pragma unroll
        for (int i = t; i < 96 * 8; i += 128) {
            int n  = i >> 3;
            int kq = i & 7;
            float4 v = *(const float4*)&Wx[(size_t)n * DMODEL + k0 + kq * 4];
            ws[kq * 4 + 0][n] = v.x;
            ws[kq * 4 + 1][n] = v.y;
            ws[kq * 4 + 2][n] = v.z;
            ws[kq * 4 + 3][n] = v.w;
        }
        __syncthreads();

#pragma unroll
        for (int kk = 0; kk < 32; kk++) {
            float a[4], b[6];
#pragma unroll
            for (int i = 0; i < 4; i++) a[i] = xs[kk][ty * 4 + i];
#pragma unroll
            for (int j = 0; j < 6; j++) b[j] = ws[kk][tx * 6 + j];
#pragma unroll
            for (int i = 0; i < 4; i++)
#pragma unroll
                for (int j = 0; j < 6; j++) acc[i][j] = fmaf(a[i], b[j], acc[i][j]);
        }
        __syncthreads();
    }

#pragma unroll
    for (int i = 0; i < 4; i++)
#pragma unroll
        for (int j = 0; j < 6; j++)
            g_proj[(size_t)(block_m + ty * 4 + i) * NPROJ + tx * 6 + j] = acc[i][j];
}

// ---------------------------------------------------------------------------
// Kernel 2: dt = softplus(dt_r @ dt_W^T + dt_b).  M=8192, N=1024, K=64.
// ---------------------------------------------------------------------------
__device__ __forceinline__ float softplusf(float z)
{
    return (z > 20.f) ? z : log1pf(__expf(z));
}

__global__ __launch_bounds__(256, 4)
void dt_gemm_kernel(const float* __restrict__ dt_W, const float* __restrict__ dt_b)
{
    __shared__ float rs[64][65];   // [k][m]
    __shared__ float ws[64][65];   // [k][n]

    const int block_m = blockIdx.x * 64;
    const int block_n = blockIdx.y * 64;
    const int t  = threadIdx.x;
    const int ty = t >> 4;
    const int tx = t & 15;

#pragma unroll
    for (int i = t; i < 64 * 16; i += 256) {
        int m  = i >> 4;
        int kq = i & 15;
        float4 v = *(const float4*)&g_proj[(size_t)(block_m + m) * NPROJ + kq * 4];
        rs[kq * 4 + 0][m] = v.x;
        rs[kq * 4 + 1][m] = v.y;
        rs[kq * 4 + 2][m] = v.z;
        rs[kq * 4 + 3][m] = v.w;
    }
#pragma unroll
    for (int i = t; i < 64 * 16; i += 256) {
        int n  = i >> 4;
        int kq = i & 15;
        float4 v = *(const float4*)&dt_W[(size_t)(block_n + n) * DTRANK + kq * 4];
        ws[kq * 4 + 0][n] = v.x;
        ws[kq * 4 + 1][n] = v.y;
        ws[kq * 4 + 2][n] = v.z;
        ws[kq * 4 + 3][n] = v.w;
    }
    __syncthreads();

    float acc[4][4];
#pragma unroll
    for (int i = 0; i < 4; i++)
#pragma unroll
        for (int j = 0; j < 4; j++) acc[i][j] = 0.f;

#pragma unroll
    for (int kk = 0; kk < 64; kk++) {
        float a[4], b[4];
#pragma unroll
        for (int i = 0; i < 4; i++) a[i] = rs[kk][ty * 4 + i];
#pragma unroll
        for (int j = 0; j < 4; j++) b[j] = ws[kk][tx * 4 + j];
#pragma unroll
        for (int i = 0; i < 4; i++)
#pragma unroll
            for (int j = 0; j < 4; j++) acc[i][j] = fmaf(a[i], b[j], acc[i][j]);
    }

    float bias[4];
#pragma unroll
    for (int j = 0; j < 4; j++) bias[j] = dt_b[block_n + tx * 4 + j];

#pragma unroll
    for (int i = 0; i < 4; i++)
#pragma unroll
        for (int j = 0; j < 4; j++)
            g_dt[(size_t)(block_m + ty * 4 + i) * DMODEL + block_n + tx * 4 + j] =
                softplusf(acc[i][j] + bias[j]);
}

// ---------------------------------------------------------------------------
// Kernel 3: selective scan with software-pipelined register prefetch.
// One thread per (d, s). Block = 128 threads = 8 d-channels.
// Loads for step l+PF are issued while computing step l, so the serial
// recurrence never waits on L2/DRAM latency.
// ---------------------------------------------------------------------------
__device__ __forceinline__ float ex2f(float z)
{
    float r;
    asm("ex2.approx.ftz.f32 %0, %1;" : "=f"(r) : "f"(z));
    return r;
}

#define PF 8   // prefetch depth (iterations ahead)

__global__ __launch_bounds__(128, 8)
void scan_kernel(const float* __restrict__ x, const float* __restrict__ A_log,
                 const float* __restrict__ Dp, float* __restrict__ out)
{
    const int b    = blockIdx.y;
    const int t    = threadIdx.x;
    const int s    = t & 15;
    const int dloc = t >> 4;
    const int d    = blockIdx.x * 8 + dloc;

    const float LOG2E = 1.4426950408889634f;
    const float A2 = -__expf(A_log[d * DSTATE + s]) * LOG2E;   // A * log2(e)
    const float Dd = Dp[d];

    const size_t base = (size_t)b * SEQLEN * DMODEL + d;
    const float* __restrict__ xb  = x    + base;
    const float* __restrict__ dtb = g_dt + base;
    const float* __restrict__ pb  = g_proj + (size_t)b * SEQLEN * NPROJ + DTRANK + s;
    float* __restrict__ ob = out + base;

    float pf_dt[PF], pf_x[PF], pf_B[PF], pf_C[PF];

    // prologue: fill pipeline
#pragma unroll
    for (int j = 0; j < PF; j++) {
        pf_dt[j] = dtb[(size_t)j * DMODEL];
        pf_x[j]  = xb[(size_t)j * DMODEL];
        pf_B[j]  = pb[j * NPROJ];
        pf_C[j]  = pb[j * NPROJ + DSTATE];
    }

    float h = 0.f;
    for (int l0 = 0; l0 < SEQLEN; l0 += PF) {
#pragma unroll
        for (int j = 0; j < PF; j++) {
            const int l = l0 + j;
            float dtv = pf_dt[j];
            float xv  = pf_x[j];
            float Bs  = pf_B[j];
            float Cs  = pf_C[j];

            // issue next-round loads immediately (independent of h chain)
            const int ln = l + PF;
            if (ln < SEQLEN) {
                pf_dt[j] = dtb[(size_t)ln * DMODEL];
                pf_x[j]  = xb[(size_t)ln * DMODEL];
                pf_B[j]  = pb[ln * NPROJ];
                pf_C[j]  = pb[ln * NPROJ + DSTATE];
            }

            float dA = ex2f(dtv * A2);
            h = fmaf(h, dA, dtv * xv * Bs);

            float p = h * Cs;
            p += __shfl_xor_sync(0xffffffffu, p, 8);
            p += __shfl_xor_sync(0xffffffffu, p, 4);
            p += __shfl_xor_sync(0xffffffffu, p, 2);
            p += __shfl_xor_sync(0xffffffffu, p, 1);

            if (s == 0) ob[(size_t)l * DMODEL] = fmaf(xv, Dd, p);
        }
    }
}

// ---------------------------------------------------------------------------
extern "C" void kernel_launch(void* const* d_in, const int* in_sizes, int n_in,
                              void* d_out, int out_size)
{
    const float* x     = (const float*)d_in[0];
    const float* A_log = (const float*)d_in[1];
    const float* D     = (const float*)d_in[2];
    const float* Wx    = (const float*)d_in[3];
    const float* dt_W  = (const float*)d_in[4];
    const float* dt_b  = (const float*)d_in[5];
    float* out = (float*)d_out;

    proj_gemm_kernel<<<NROWS / 32, 128>>>(x, Wx);
    dt_gemm_kernel<<<dim3(NROWS / 64, DMODEL / 64), 256>>>(dt_W, dt_b);
    scan_kernel<<<dim3(DMODEL / 8, BATCH), 128>>>(x, A_log, D, out);
}